// round 7
// baseline (speedup 1.0000x reference)
#include <cuda_runtime.h>
#include <stdint.h>

#define IN_F   1024
#define OUT_F  512
#define BATCH  256
#define HALF_OUT (OUT_F / 2)

typedef unsigned long long ull;

// Parity-split transposed masks: [word][o>>1], word = i>>5; bit set == EDGE.
// Even-o array serves the min outputs, odd-o the max outputs; reduce threads
// then index column t directly -> fully coalesced mask loads.
__device__ uint32_t d_maskT_e[(IN_F / 32) * HALF_OUT];
__device__ uint32_t d_maskT_o[(IN_F / 32) * HALF_OUT];
// Per-batch-row bucket-grouped elements: packed (float_bits<<32 | bucket<<10 | idx)
__device__ ull d_sorted[BATCH * IN_F];

#define SORT_BLOCKS  BATCH            // 256
#define MASK_BLOCKS  256              // 256 blk * 8 warps * 256 pairs = 512K pairs
#define THREADS      256

// ---------------------------------------------------------------------------
// Fused prep: blocks [0,256) counting-sort one x row each;
// blocks [256,512) compute the edge mask, 8 pairs/thread (16 loads in flight).
// ---------------------------------------------------------------------------
__global__ void prep_kernel(const float* __restrict__ x,
                            const float* __restrict__ etc,
                            const float* __restrict__ un) {
    __shared__ uint32_t hist[IN_F];
    __shared__ uint32_t wsum[8];

    int t = threadIdx.x;

    if (blockIdx.x >= SORT_BLOCKS) {
        // ---------------- MASK: 8 lane-strided pairs per thread ------------
        int mb     = blockIdx.x - SORT_BLOCKS;
        int warp_g = (mb * THREADS + t) >> 5;   // 2048 warps total
        int lane   = t & 31;
        int base   = warp_g * 256;              // 256 pairs per warp (one o row)

        float2 e[8], u[8];
#pragma unroll
        for (int g = 0; g < 8; g++) {
            int p = base + g * 32 + lane;
            e[g] = reinterpret_cast<const float2*>(etc)[p];
            u[g] = reinterpret_cast<const float2*>(un)[p];
        }
#pragma unroll
        for (int g = 0; g < 8; g++) {
            int p = base + g * 32 + lane;
            bool no_edge;
            if (e[g].x == e[g].y) {
                no_edge = (u[g].y > u[g].x);    // gumbel monotone in uniform
            } else {
                const float eps = 1e-10f;
                float g0 = -logf(-logf(u[g].x + eps) + eps);
                float g1 = -logf(-logf(u[g].y + eps) + eps);
                no_edge = (e[g].y + g1) > (e[g].x + g0);
            }
            uint32_t m = __ballot_sync(0xffffffffu, !no_edge);
            if (lane == 0) {
                int i = p & (IN_F - 1);
                int o = p >> 10;                // warp-uniform
                uint32_t* arr = (o & 1) ? d_maskT_o : d_maskT_e;
                arr[(i >> 5) * HALF_OUT + (o >> 1)] = m;
            }
        }
        return;
    }

    // ---------------- SORT: counting sort of one batch row -----------------
    int b = blockIdx.x;

    for (int k = t; k < IN_F; k += THREADS) hist[k] = 0;
    __syncthreads();

    float4 v4 = reinterpret_cast<const float4*>(x + b * IN_F)[t];
    float vals[4] = {v4.x, v4.y, v4.z, v4.w};
    int   bkt[4];
#pragma unroll
    for (int q = 0; q < 4; q++) {
        int bb = (int)(vals[q] * 1024.0f);
        bb = bb > 1023 ? 1023 : (bb < 0 ? 0 : bb);
        bkt[q] = bb;
        atomicAdd(&hist[bb], 1u);
    }
    __syncthreads();

    uint32_t h0 = hist[t * 4 + 0], h1 = hist[t * 4 + 1];
    uint32_t h2 = hist[t * 4 + 2], h3 = hist[t * 4 + 3];
    uint32_t s = h0 + h1 + h2 + h3;

    int lane = t & 31, w = t >> 5;
    uint32_t ss = s;
#pragma unroll
    for (int d = 1; d < 32; d <<= 1) {
        uint32_t n = __shfl_up_sync(0xffffffffu, ss, d);
        if (lane >= d) ss += n;
    }
    if (lane == 31) wsum[w] = ss;
    __syncthreads();
    if (t == 0) {
        uint32_t r = 0;
#pragma unroll
        for (int k = 0; k < 8; k++) { uint32_t v = wsum[k]; wsum[k] = r; r += v; }
    }
    __syncthreads();
    uint32_t excl = ss - s + wsum[w];
    __syncthreads();
    hist[t * 4 + 0] = excl;
    hist[t * 4 + 1] = excl + h0;
    hist[t * 4 + 2] = excl + h0 + h1;
    hist[t * 4 + 3] = excl + h0 + h1 + h2;
    __syncthreads();

#pragma unroll
    for (int q = 0; q < 4; q++) {
        int i = t * 4 + q;
        uint32_t pos = atomicAdd(&hist[bkt[q]], 1u);
        ull key = ((ull)__float_as_uint(vals[q]) << 32) |
                  ((ull)(uint32_t)bkt[q] << 10) |
                  (ull)(uint32_t)i;
        d_sorted[b * IN_F + pos] = key;
    }
}

// ---------------------------------------------------------------------------
// Reduce v5: 512 blocks x 256 threads; blk=(b,half). half 0 = min over even o
// (ascending), half 1 = max over odd o (descending).
// Stage 1: 16 threads stage the warp-uniform probe entries into SMEM
//          (broadcast LDS replaces 32 SHFLs/thread).
// Stage 2: 16 independent, FULLY COALESCED mask loads (parity-split mask,
//          column == threadIdx).
// Stage 3: register-only hit-mask scan; divergent but sync-free.
// ---------------------------------------------------------------------------
#define DEPTH 16

__global__ void reduce_kernel(float* __restrict__ out) {
    __shared__ ull se[DEPTH];

    int blk  = blockIdx.x;
    int b    = blk >> 1;
    int half = blk & 1;                 // 0 -> min/even o, 1 -> max/odd o
    int t    = threadIdx.x;             // 256; also the mask-array column
    int o    = 2 * t + half;

    const ull* srt = d_sorted + b * IN_F;
    const uint32_t* mT = half ? d_maskT_o : d_maskT_e;

    if (t < DEPTH)
        se[t] = half ? srt[IN_F - 1 - t] : srt[t];   // one coalesced LDG.64
    __syncthreads();

    ull e[DEPTH];
#pragma unroll
    for (int k = 0; k < DEPTH; k++) e[k] = se[k];    // broadcast LDS

    // 16 independent coalesced mask loads -> 16-bit hit mask
    uint32_t hit = 0;
#pragma unroll
    for (int k = 0; k < DEPTH; k++) {
        int idx = (int)(e[k] & 1023u);
        uint32_t w = mT[(idx >> 5) * HALF_OUT + t];
        hit |= ((w >> (idx & 31)) & 1u) << k;
    }

    // Register-only scan (state: 0 = searching, 1 = in first-hit bucket, 2 = done)
    float acc   = half ? -1.0f : 2.0f;  // no-edge offsets
    int   state = 0;
    int   bkt_h = -1;

#pragma unroll
    for (int k = 0; k < DEPTH; k++) {
        int  bkt = (int)((e[k] >> 10) & 1023u);
        bool hk  = (hit >> k) & 1u;
        if (state == 0) {
            if (hk) { bkt_h = bkt; acc = __uint_as_float((uint32_t)(e[k] >> 32)); state = 1; }
        } else if (state == 1) {
            if (bkt != bkt_h) state = 2;
            else if (hk) {
                float v = __uint_as_float((uint32_t)(e[k] >> 32));
                acc = half ? fmaxf(acc, v) : fminf(acc, v);
            }
        }
    }

    if (state != 2) {                   // ~2^-16 per thread: sequential tail
        bool found = (state == 1);
        for (int k = DEPTH; k < IN_F; k++) {
            ull ee = half ? srt[IN_F - 1 - k] : srt[k];
            int bkt = (int)((ee >> 10) & 1023u);
            if (found && bkt != bkt_h) break;
            int idx = (int)(ee & 1023u);
            uint32_t wd = mT[(idx >> 5) * HALF_OUT + t];
            if ((wd >> (idx & 31)) & 1u) {
                float v = __uint_as_float((uint32_t)(ee >> 32));
                if (!found) { found = true; bkt_h = bkt; acc = v; }
                else        { acc = half ? fmaxf(acc, v) : fminf(acc, v); }
            }
        }
    }

    out[b * OUT_F + o] = acc;
}

// ---------------------------------------------------------------------------
extern "C" void kernel_launch(void* const* d_in, const int* in_sizes, int n_in,
                              void* d_out, int out_size) {
    const float* x    = (const float*)d_in[0];   // [256,1024]
    const float* etc  = (const float*)d_in[1];   // [512,1024,2]
    const float* un   = (const float*)d_in[2];   // [512,1024,2]
    float* out = (float*)d_out;                  // [256,512]

    prep_kernel<<<SORT_BLOCKS + MASK_BLOCKS, THREADS>>>(x, etc, un);
    reduce_kernel<<<BATCH * 2, THREADS>>>(out);
}

// round 9
// speedup vs baseline: 1.0025x; 1.0025x over previous
#include <cuda_runtime.h>
#include <stdint.h>

#define IN_F   1024
#define OUT_F  512
#define BATCH  256
#define HALF_OUT (OUT_F / 2)

typedef unsigned long long ull;

// Parity-split transposed masks: [word][o>>1], word = i>>5; bit set == EDGE.
__device__ uint32_t d_maskT_e[(IN_F / 32) * HALF_OUT];
__device__ uint32_t d_maskT_o[(IN_F / 32) * HALF_OUT];
// Per-batch-row bucket-grouped elements: packed (float_bits<<32 | bucket<<10 | idx)
__device__ ull d_sorted[BATCH * IN_F];
// Grid-barrier counter: monotone across graph replays (never reset; signed
// wraparound compare). Each launch consumes exactly GRID arrivals.
__device__ unsigned d_bar;

#define SORT_BLOCKS  BATCH            // 256
#define MASK_BLOCKS  256
#define GRID         (SORT_BLOCKS + MASK_BLOCKS)   // 512, all co-resident
#define THREADS      256

// ---------------------------------------------------------------------------
// ONE persistent kernel: phase 1 prep (sort blocks / mask blocks), software
// grid barrier, phase 2 reduce (all blocks).
// __launch_bounds__(256,4): 4 CTAs/SM * 148 SMs = 592 >= 512 -> all resident,
// so the spin barrier cannot deadlock.
// ---------------------------------------------------------------------------
__global__ __launch_bounds__(THREADS, 4)
void fused_kernel(const float* __restrict__ x,
                  const float* __restrict__ etc,
                  const float* __restrict__ un,
                  float* __restrict__ out) {
    __shared__ uint32_t hist[IN_F];
    __shared__ uint32_t wsum[8];
    __shared__ ull      se[8][16];     // per-warp probe staging (reduce phase)

    int t = threadIdx.x;

    // ======================= PHASE 1: PREP =================================
    if (blockIdx.x >= SORT_BLOCKS) {
        // ---- MASK: 8 lane-strided pairs per thread (16 loads in flight) ----
        int mb     = blockIdx.x - SORT_BLOCKS;
        int warp_g = (mb * THREADS + t) >> 5;
        int lane   = t & 31;
        int base   = warp_g * 256;          // 256 pairs per warp (one o row)

        float2 e[8], u[8];
#pragma unroll
        for (int g = 0; g < 8; g++) {
            int p = base + g * 32 + lane;
            e[g] = reinterpret_cast<const float2*>(etc)[p];
            u[g] = reinterpret_cast<const float2*>(un)[p];
        }
#pragma unroll
        for (int g = 0; g < 8; g++) {
            int p = base + g * 32 + lane;
            bool no_edge;
            if (e[g].x == e[g].y) {
                no_edge = (u[g].y > u[g].x);   // gumbel monotone in uniform
            } else {
                const float eps = 1e-10f;
                float g0 = -logf(-logf(u[g].x + eps) + eps);
                float g1 = -logf(-logf(u[g].y + eps) + eps);
                no_edge = (e[g].y + g1) > (e[g].x + g0);
            }
            uint32_t m = __ballot_sync(0xffffffffu, !no_edge);
            if (lane == 0) {
                int i = p & (IN_F - 1);
                int o = p >> 10;               // warp-uniform
                uint32_t* arr = (o & 1) ? d_maskT_o : d_maskT_e;
                arr[(i >> 5) * HALF_OUT + (o >> 1)] = m;
            }
        }
    } else {
        // ---- SORT: counting sort of one batch row -------------------------
        int b = blockIdx.x;

        for (int k = t; k < IN_F; k += THREADS) hist[k] = 0;
        __syncthreads();

        float4 v4 = reinterpret_cast<const float4*>(x + b * IN_F)[t];
        float vals[4] = {v4.x, v4.y, v4.z, v4.w};
        int   bkt[4];
#pragma unroll
        for (int q = 0; q < 4; q++) {
            int bb = (int)(vals[q] * 1024.0f);
            bb = bb > 1023 ? 1023 : (bb < 0 ? 0 : bb);
            bkt[q] = bb;
            atomicAdd(&hist[bb], 1u);
        }
        __syncthreads();

        uint32_t h0 = hist[t * 4 + 0], h1 = hist[t * 4 + 1];
        uint32_t h2 = hist[t * 4 + 2], h3 = hist[t * 4 + 3];
        uint32_t s = h0 + h1 + h2 + h3;

        int lane = t & 31, w = t >> 5;
        uint32_t ss = s;
#pragma unroll
        for (int d = 1; d < 32; d <<= 1) {
            uint32_t n = __shfl_up_sync(0xffffffffu, ss, d);
            if (lane >= d) ss += n;
        }
        if (lane == 31) wsum[w] = ss;
        __syncthreads();
        if (t == 0) {
            uint32_t r = 0;
#pragma unroll
            for (int k = 0; k < 8; k++) { uint32_t v = wsum[k]; wsum[k] = r; r += v; }
        }
        __syncthreads();
        uint32_t excl = ss - s + wsum[w];
        __syncthreads();
        hist[t * 4 + 0] = excl;
        hist[t * 4 + 1] = excl + h0;
        hist[t * 4 + 2] = excl + h0 + h1;
        hist[t * 4 + 3] = excl + h0 + h1 + h2;
        __syncthreads();

#pragma unroll
        for (int q = 0; q < 4; q++) {
            int i = t * 4 + q;
            uint32_t pos = atomicAdd(&hist[bkt[q]], 1u);
            ull key = ((ull)__float_as_uint(vals[q]) << 32) |
                      ((ull)(uint32_t)bkt[q] << 10) |
                      (ull)(uint32_t)i;
            d_sorted[b * IN_F + pos] = key;
        }
    }

    // ======================= GRID BARRIER ==================================
    __threadfence();                        // release prep writes (gpu scope)
    if (t == 0) {
        unsigned old = atomicAdd(&d_bar, 1u);
        unsigned tgt = (old & ~(unsigned)(GRID - 1)) + GRID;  // GRID is pow2
        while ((int)(*(volatile unsigned*)&d_bar - tgt) < 0)
            __nanosleep(64);
    }
    __syncthreads();
    __threadfence();                        // acquire for all threads

    // ======================= PHASE 2: REDUCE ===============================
    {
        int blk  = blockIdx.x;
        int b    = blk >> 1;
        int half = blk & 1;                 // 0 -> min/even o, 1 -> max/odd o
        int warp = t >> 5, lane = t & 31;

        const ull* srt = d_sorted + b * IN_F;
        const uint32_t* mT = half ? d_maskT_o : d_maskT_e;

        // ---- window 0: stage 8 entries per warp, probe branchlessly -------
        if (lane < 8)
            se[warp][lane] = half ? srt[IN_F - 1 - lane] : srt[lane];
        __syncwarp();

        float acc = half ? -1.0f : 2.0f;    // sentinel == no-edge offset
        uint32_t hit = 0;
        int bktLast = 0;
#pragma unroll
        for (int k = 0; k < 8; k++) {
            ull ek = se[warp][k];
            uint32_t lo = (uint32_t)ek;
            int idx = lo & 1023;
            int bkt = (lo >> 10) & 1023;
            float v = __uint_as_float((uint32_t)(ek >> 32));
            uint32_t wd = mT[((idx >> 5) << 8) + t];
            if ((wd >> (idx & 31)) & 1u) {
                acc = half ? fmaxf(acc, v) : fminf(acc, v);
                hit |= 1u << k;
            }
            if (k == 7) bktLast = bkt;
        }
        int kEnd = 8;

        // ---- window 1 (warp-uniform vote, ~12% of warps) ------------------
        if (__any_sync(0xffffffffu, hit == 0)) {
            if (lane < 8)
                se[warp][8 + lane] = half ? srt[IN_F - 9 - lane] : srt[8 + lane];
            __syncwarp();
            if (hit == 0) {
#pragma unroll
                for (int k = 8; k < 16; k++) {
                    ull ek = se[warp][k];
                    uint32_t lo = (uint32_t)ek;
                    int idx = lo & 1023;
                    int bkt = (lo >> 10) & 1023;
                    float v = __uint_as_float((uint32_t)(ek >> 32));
                    uint32_t wd = mT[((idx >> 5) << 8) + t];
                    if ((wd >> (idx & 31)) & 1u) {
                        acc = half ? fmaxf(acc, v) : fminf(acc, v);
                        hit |= 1u << k;
                    }
                    if (k == 15) bktLast = bkt;
                }
                kEnd = 16;
            }
        }

        // ---- resolution / rare tails (register-only divergence, no sync) --
        if (hit == 0) {
            // ~2^-16 per thread: full generic walk from kEnd
            bool found = false; int bf = -1;
            for (int k = kEnd; k < IN_F; k++) {
                ull ee = half ? srt[IN_F - 1 - k] : srt[k];
                int bkt = (int)((ee >> 10) & 1023u);
                if (found && bkt != bf) break;
                int idx = (int)(ee & 1023u);
                uint32_t wd = mT[((idx >> 5) << 8) + t];
                if ((wd >> (idx & 31)) & 1u) {
                    float v = __uint_as_float((uint32_t)(ee >> 32));
                    if (!found) { found = true; bf = bkt; acc = v; }
                    else        { acc = half ? fmaxf(acc, v) : fminf(acc, v); }
                }
            }
        } else {
            // spill: extremum's bucket may extend past the probed window
            int bf = (int)(acc * 1024.0f);
            bf = bf > 1023 ? 1023 : (bf < 0 ? 0 : bf);
            if (bf == bktLast) {
                for (int k = kEnd; k < IN_F; k++) {
                    ull ee = half ? srt[IN_F - 1 - k] : srt[k];
                    int bkt = (int)((ee >> 10) & 1023u);
                    if (bkt != bf) break;
                    int idx = (int)(ee & 1023u);
                    uint32_t wd = mT[((idx >> 5) << 8) + t];
                    if ((wd >> (idx & 31)) & 1u) {
                        float v = __uint_as_float((uint32_t)(ee >> 32));
                        acc = half ? fmaxf(acc, v) : fminf(acc, v);
                    }
                }
            }
        }

        out[b * OUT_F + 2 * t + half] = acc;
    }
}

// ---------------------------------------------------------------------------
extern "C" void kernel_launch(void* const* d_in, const int* in_sizes, int n_in,
                              void* d_out, int out_size) {
    const float* x    = (const float*)d_in[0];   // [256,1024]
    const float* etc  = (const float*)d_in[1];   // [512,1024,2]
    const float* un   = (const float*)d_in[2];   // [512,1024,2]
    float* out = (float*)d_out;                  // [256,512]

    fused_kernel<<<GRID, THREADS>>>(x, etc, un, out);
}